// round 12
// baseline (speedup 1.0000x reference)
#include <cuda_runtime.h>
#include <cuda_bf16.h>
#include <cstdint>

// ---------------------------------------------------------------------------
// EfmLSTM round 12: GEMM/conv = round 11. Scan = joint 2-row (round-10 body)
// with HYBRID W: k<64 in registers (64 regs), k>=64 streamed from 96KB SMEM
// (swizzled, conflict-free) -> regs 168->~135 so ptxas can hoist LDS loads.
// ---------------------------------------------------------------------------

#define B_   256
#define T_   1024
#define D_   256
#define U_   128
#define G_   384
#define SIG_ 20
#define M_   (B_ * T_)

typedef unsigned long long ull;

__device__ float g_xproj[(size_t)M_ * G_];
__device__ __nv_bfloat16 g_acat[(size_t)M_ * 512];
__device__ __nv_bfloat16 g_btcat[(size_t)G_ * 768];
__device__ float g_gbias[G_];

__device__ __forceinline__ ull pack2f(float lo, float hi) {
    ull r; asm("mov.b64 %0, {%1,%2};" : "=l"(r) : "f"(lo), "f"(hi)); return r;
}
__device__ __forceinline__ void unpack2f(ull v, float& lo, float& hi) {
    asm("mov.b64 {%0,%1}, %2;" : "=f"(lo), "=f"(hi) : "l"(v));
}
__device__ __forceinline__ ull ffma2(ull a, ull b, ull c) {
    ull d; asm("fma.rn.f32x2 %0, %1, %2, %3;" : "=l"(d) : "l"(a), "l"(b), "l"(c)); return d;
}
__device__ __forceinline__ float fsig(float x) {
    return __fdividef(1.0f, 1.0f + __expf(-x));
}
__device__ __forceinline__ float ftanh(float x) {
    return 1.0f - 2.0f * __fdividef(1.0f, __expf(2.0f * x) + 1.0f);
}
__device__ __forceinline__ uint32_t smem_u32(const void* p) {
    uint32_t a;
    asm("{ .reg .u64 t; cvta.to.shared.u64 t, %1; cvt.u32.u64 %0, t; }" : "=r"(a) : "l"(p));
    return a;
}
__device__ __forceinline__ void ldsm4(uint32_t* r, uint32_t addr) {
    asm volatile("ldmatrix.sync.aligned.m8n8.x4.shared.b16 {%0,%1,%2,%3}, [%4];"
        : "=r"(r[0]), "=r"(r[1]), "=r"(r[2]), "=r"(r[3]) : "r"(addr));
}
__device__ __forceinline__ void mma16816(float* d, const uint32_t* a, const uint32_t* b) {
    asm volatile(
        "mma.sync.aligned.m16n8k16.row.col.f32.bf16.bf16.f32 "
        "{%0,%1,%2,%3}, {%4,%5,%6,%7}, {%8,%9}, {%0,%1,%2,%3};"
        : "+f"(d[0]), "+f"(d[1]), "+f"(d[2]), "+f"(d[3])
        : "r"(a[0]), "r"(a[1]), "r"(a[2]), "r"(a[3]), "r"(b[0]), "r"(b[1]));
}
__device__ __forceinline__ void cpasync16(uint32_t dst, const void* src) {
    asm volatile("cp.async.cg.shared.global [%0], [%1], 16;" :: "r"(dst), "l"(src) : "memory");
}
#define CP_COMMIT() asm volatile("cp.async.commit_group;" ::: "memory")
#define CP_WAITG(n) asm volatile("cp.async.wait_group %0;" :: "n"(n) : "memory")

// ===========================================================================
__global__ __launch_bounds__(256)
void conv_a(const float* __restrict__ in) {
    size_t v = (size_t)blockIdx.x * 256 + threadIdx.x;
    size_t m = v >> 6;
    int c4 = (int)(v & 63);
    float4 a = ((const float4*)in)[v];
    __nv_bfloat16 h0 = __float2bfloat16(a.x), h1 = __float2bfloat16(a.y);
    __nv_bfloat16 h2 = __float2bfloat16(a.z), h3 = __float2bfloat16(a.w);
    __nv_bfloat16 l0 = __float2bfloat16(a.x - __bfloat162float(h0));
    __nv_bfloat16 l1 = __float2bfloat16(a.y - __bfloat162float(h1));
    __nv_bfloat16 l2 = __float2bfloat16(a.z - __bfloat162float(h2));
    __nv_bfloat16 l3 = __float2bfloat16(a.w - __bfloat162float(h3));
    __nv_bfloat162* dst = (__nv_bfloat162*)(g_acat + m * 512 + c4 * 4);
    dst[0] = __nv_bfloat162(h0, h1);
    dst[1] = __nv_bfloat162(h2, h3);
    __nv_bfloat162* dstl = (__nv_bfloat162*)(g_acat + m * 512 + 256 + c4 * 4);
    dstl[0] = __nv_bfloat162(l0, l1);
    dstl[1] = __nv_bfloat162(l2, l3);
}

// ===========================================================================
__global__ __launch_bounds__(384)
void conv_b(const float* __restrict__ ik, const float* __restrict__ bias) {
    int k = blockIdx.x;
    int n = threadIdx.x;
    float b = ik[(size_t)k * G_ + n];
    __nv_bfloat16 bh = __float2bfloat16(b);
    __nv_bfloat16 bl = __float2bfloat16(b - __bfloat162float(bh));
    __nv_bfloat16* row = g_btcat + (size_t)n * 768;
    row[k] = bh;
    row[256 + k] = bh;
    row[512 + k] = bl;
    if (k == 0) {
        float gb;
        if (n < U_)          gb = bias[n];
        else if (n < 2 * U_) gb = bias[2 * U_ + (n - U_)];
        else                 gb = bias[3 * U_ + (n - 2 * U_)];
        g_gbias[n] = gb;
    }
}

// ===========================================================================
// K1: x_proj GEMM (round-7 pipeline) + gate bias in epilogue.
// ===========================================================================
#define ABUF(s) ((s) * 16384)
#define BBUF(s) (49152 + (s) * 16384)

__global__ __launch_bounds__(256, 2)
void xproj_mma(void) {
    extern __shared__ __align__(1024) char dsm[];
    const uint32_t sb = smem_u32(dsm);

    const int tid = threadIdx.x;
    const int wid = tid >> 5;
    const int lane = tid & 31;
    const int wm = wid & 3;
    const int wn = wid >> 2;
    const int n0 = blockIdx.x * 128;
    const size_t m0 = (size_t)blockIdx.y * 128;

    const int lrow = tid >> 3;
    const int c16  = tid & 7;
    uint32_t cpOff[4];
#pragma unroll
    for (int i = 0; i < 4; i++) {
        int row = lrow + 32 * i;
        cpOff[i] = (uint32_t)(row * 128 + ((c16 * 16) ^ ((row & 7) << 4)));
    }
    const __nv_bfloat16* aSrc[4];
    const __nv_bfloat16* bSrc[4];
#pragma unroll
    for (int i = 0; i < 4; i++) {
        int row = lrow + 32 * i;
        aSrc[i] = g_acat + (m0 + row) * 512 + c16 * 8;
        bSrc[i] = g_btcat + (size_t)(n0 + row) * 768 + c16 * 8;
    }

    const int a_row0 = wm * 32 + (lane & 15);
    const int a_hi   = lane >> 4;
    const uint32_t a_xor = (uint32_t)((a_row0 & 7) << 4);
    const uint32_t aOff0 = (uint32_t)(a_row0 * 128);
    const uint32_t aOff1 = (uint32_t)((a_row0 + 16) * 128);

    const int b_row_l = wn * 64 + (lane & 7) + ((lane >> 4) << 3);
    const int b_hi    = (lane >> 3) & 1;
    const uint32_t b_xor = (uint32_t)((b_row_l & 7) << 4);
    uint32_t bOff[4];
#pragma unroll
    for (int p = 0; p < 4; p++)
        bOff[p] = (uint32_t)((b_row_l + p * 16) * 128);

    float d[2][8][4];
#pragma unroll
    for (int af = 0; af < 2; af++)
#pragma unroll
        for (int p = 0; p < 8; p++)
#pragma unroll
            for (int q = 0; q < 4; q++) d[af][p][q] = 0.0f;

#pragma unroll
    for (int pc = 0; pc < 2; pc++) {
#pragma unroll
        for (int i = 0; i < 4; i++) cpasync16(sb + ABUF(pc) + cpOff[i], aSrc[i] + pc * 64);
#pragma unroll
        for (int i = 0; i < 4; i++) cpasync16(sb + BBUF(pc) + cpOff[i], bSrc[i] + pc * 64);
        CP_COMMIT();
    }

#pragma unroll
    for (int c = 0; c < 12; c++) {
        const int buf = c % 3;

        if (c < 11) { CP_WAITG(1); } else { CP_WAITG(0); }
        __syncthreads();

        if (c + 2 < 12) {
            const int cn = c + 2;
            const int nbuf = cn % 3;
            const int akc = (cn < 8) ? cn * 64 : (cn - 8) * 64;
            const int bkc = cn * 64;
#pragma unroll
            for (int i = 0; i < 4; i++) cpasync16(sb + ABUF(nbuf) + cpOff[i], aSrc[i] + akc);
#pragma unroll
            for (int i = 0; i < 4; i++) cpasync16(sb + BBUF(nbuf) + cpOff[i], bSrc[i] + bkc);
            CP_COMMIT();
        }

        const uint32_t aB0 = sb + ABUF(buf) + aOff0;
        const uint32_t aB1 = sb + ABUF(buf) + aOff1;
        const uint32_t bBs = sb + BBUF(buf);
#pragma unroll
        for (int ks = 0; ks < 4; ks++) {
            uint32_t af0[4], af1[4];
            uint32_t koffA = (uint32_t)(((ks * 2 + a_hi) * 16) ^ a_xor);
            ldsm4(af0, aB0 + koffA);
            ldsm4(af1, aB1 + koffA);
            uint32_t koffB = (uint32_t)(((ks * 2 + b_hi) * 16) ^ b_xor);
#pragma unroll
            for (int p = 0; p < 4; p++) {
                uint32_t bf[4];
                ldsm4(bf, bBs + bOff[p] + koffB);
                mma16816(d[0][p * 2],     af0, &bf[0]);
                mma16816(d[0][p * 2 + 1], af0, &bf[2]);
                mma16816(d[1][p * 2],     af1, &bf[0]);
                mma16816(d[1][p * 2 + 1], af1, &bf[2]);
            }
        }
    }

    const int colb = n0 + wn * 64 + 2 * (lane & 3);
#pragma unroll
    for (int af = 0; af < 2; af++) {
        const int mrow = (int)m0 + wm * 32 + af * 16 + (lane >> 2);
#pragma unroll
        for (int p = 0; p < 8; p++) {
            int col = colb + p * 8;
            float2 gb = *(const float2*)(g_gbias + col);
            *(float2*)(g_xproj + (size_t)mrow * G_ + col) =
                make_float2(d[af][p][0] + gb.x, d[af][p][1] + gb.y);
            *(float2*)(g_xproj + (size_t)(mrow + 8) * G_ + col) =
                make_float2(d[af][p][2] + gb.x, d[af][p][3] + gb.y);
        }
    }
}

// ===========================================================================
// K2: joint 2-row scan, hybrid W.
// W k<64: 32 packed ull in registers. W k>=64: SMEM sW, thread j's row at
// sW + j*256, 16B chunk c at ((c ^ (j&7))*16) — conflict-free per 8-lane phase.
// ===========================================================================
__global__ __launch_bounds__(384, 1)
void efm_scan(const float* __restrict__ sigs,
              const float* __restrict__ rk,
              const float* __restrict__ fk,
              const float* __restrict__ bias,
              float* __restrict__ out)
{
    extern __shared__ __align__(16) char swdyn[];   // 384*256 = 98304 B
    const uint32_t sWb = smem_u32(swdyn);

    const int j = threadIdx.x;
    const int r0 = blockIdx.x * 2;

    __shared__ __align__(16) float sh[2][U_];
    __shared__ __align__(16) float sg[2][G_];
    __shared__ __align__(16) float sF[SIG_][U_];
    __shared__ float ssig[2][2][SIG_];
    __shared__ float sfv[2][2][U_];

    // --- W k<64 in registers: 32 packed pairs ---
    ull W[32];
#pragma unroll
    for (int k2 = 0; k2 < 32; k2++)
        W[k2] = pack2f(rk[(2 * k2) * G_ + j], rk[(2 * k2 + 1) * G_ + j]);

    // --- W k>=64 into SMEM (swizzled) ---
    const uint32_t sWrow = sWb + (uint32_t)j * 256;
#pragma unroll
    for (int c = 0; c < 16; c++) {
        int k = 64 + 4 * c;
        float4 v;
        v.x = rk[(size_t)k * G_ + j];
        v.y = rk[(size_t)(k + 1) * G_ + j];
        v.z = rk[(size_t)(k + 2) * G_ + j];
        v.w = rk[(size_t)(k + 3) * G_ + j];
        *(float4*)(swdyn + (size_t)j * 256 + ((c ^ (j & 7)) * 16)) = v;
    }

    for (int idx = j; idx < SIG_ * U_; idx += 384)
        (&sF[0][0])[idx] = fk[idx];

    if (j < U_) { sh[0][j] = 0.0f; sh[1][j] = 0.0f; }

    const int brow = (j < U_) ? 0 : 1;
    const int u = j & (U_ - 1);
    float creg = 0.0f;
    float* op = out + ((size_t)(r0 + ((j < 2 * U_) ? brow : 0)) * T_) * U_ + u;

    const int fidx = (j - 128) & 255;
    const int frow = fidx >> 7;
    const int fu   = fidx & 127;
    const bool isF = (j >= 128);
    const float fbias = bias[U_ + fu];

    const bool isL = (j >= 256) && (j < 256 + 2 * SIG_);
    const int srow = isL ? (j - 256) / SIG_ : 0;
    const int ss   = isL ? (j - 256) % SIG_ : 0;
    const float* sigp = sigs + ((size_t)(r0 + srow) * T_) * SIG_ + ss;

    if (isL) ssig[0][srow][ss] = sigp[0];
    float sreg = isL ? sigp[SIG_] : 0.0f;
    float x0 = g_xproj[((size_t)r0 * T_) * G_ + j];
    float x1 = g_xproj[((size_t)(r0 + 1) * T_) * G_ + j];
    __syncthreads();

    if (isF) {
        float a = fbias;
#pragma unroll
        for (int s = 0; s < SIG_; s++) a += ssig[0][frow][s] * sF[s][fu];
        sfv[0][frow][fu] = fsig(a);
    }
    __syncthreads();

    for (int t = 0; t < T_; t++) {
        if (isL) {
            ssig[(t + 1) & 1][srow][ss] = sreg;
            int t2 = (t + 2 < T_) ? (t + 2) : (T_ - 1);
            sreg = sigp[(size_t)t2 * SIG_];
        }
        float nx0 = 0.0f, nx1 = 0.0f;
        if (t + 1 < T_) {
            nx0 = g_xproj[((size_t)r0 * T_ + t + 1) * G_ + j];
            nx1 = g_xproj[((size_t)(r0 + 1) * T_ + t + 1) * G_ + j];
        }
        float fcur = (j < 2 * U_) ? sfv[t & 1][brow][u] : 0.0f;

        // --- GEMV: k<64 from register W, k>=64 from SMEM W; same chains ---
        const ulonglong2* hp0 = (const ulonglong2*)sh[0];
        const ulonglong2* hp1 = (const ulonglong2*)sh[1];
        ull acA0 = 0ULL, acB0 = 0ULL, acA1 = 0ULL, acB1 = 0ULL;
#pragma unroll
        for (int q = 0; q < 16; q++) {
            ulonglong2 h0 = hp0[q];
            ulonglong2 h1 = hp1[q];
            acA0 = ffma2(h0.x, W[2 * q],     acA0);
            acB0 = ffma2(h0.y, W[2 * q + 1], acB0);
            acA1 = ffma2(h1.x, W[2 * q],     acA1);
            acB1 = ffma2(h1.y, W[2 * q + 1], acB1);
        }
#pragma unroll
        for (int c = 0; c < 16; c++) {
            ulonglong2 wv = *(const ulonglong2*)(swdyn + (size_t)j * 256 + ((c ^ (j & 7)) * 16));
            ulonglong2 h0 = hp0[16 + c];
            ulonglong2 h1 = hp1[16 + c];
            acA0 = ffma2(h0.x, wv.x, acA0);
            acB0 = ffma2(h0.y, wv.y, acB0);
            acA1 = ffma2(h1.x, wv.x, acA1);
            acB1 = ffma2(h1.y, wv.y, acB1);
        }
        float lo, hi;
        unpack2f(acA0, lo, hi); float g0 = lo + hi;
        unpack2f(acB0, lo, hi); g0 += lo + hi;
        g0 += x0;
        unpack2f(acA1, lo, hi); float g1 = lo + hi;
        unpack2f(acB1, lo, hi); g1 += lo + hi;
        g1 += x1;

        float act0, act1;
        if (j < U_ || j >= 2 * U_) { act0 = fsig(g0);  act1 = fsig(g1);  }
        else                       { act0 = ftanh(g0); act1 = ftanh(g1); }
        sg[0][j] = act0;
        sg[1][j] = act1;
        __syncthreads();   // barrier 1

        if (j < 2 * U_) {
            float ig = sg[brow][u];
            float ch = sg[brow][U_ + u];
            float og = sg[brow][2 * U_ + u];
            creg = fcur * creg + ig * ch;
            float hn = og * ftanh(creg);
            sh[brow][u] = hn;
            op[(size_t)t * U_] = hn;
        }
        if (isF) {
            float a = fbias;
#pragma unroll
            for (int s = 0; s < SIG_; s++)
                a += ssig[(t + 1) & 1][frow][s] * sF[s][fu];
            sfv[(t + 1) & 1][frow][fu] = fsig(a);
        }
        __syncthreads();   // barrier 2

        x0 = nx0;
        x1 = nx1;
    }
}

// ===========================================================================
extern "C" void kernel_launch(void* const* d_in, const int* in_sizes, int n_in,
                              void* d_out, int out_size) {
    const float* inputs = (const float*)d_in[0];
    const float* sigs   = (const float*)d_in[1];
    const float* ik     = (const float*)d_in[2];
    const float* rk     = (const float*)d_in[3];
    const float* fk     = (const float*)d_in[4];
    const float* bias   = (const float*)d_in[5];
    float* out = (float*)d_out;

    cudaFuncSetAttribute(xproj_mma, cudaFuncAttributeMaxDynamicSharedMemorySize, 98304);
    cudaFuncSetAttribute(efm_scan, cudaFuncAttributeMaxDynamicSharedMemorySize, 98304);

    conv_a<<<(M_ * 64) / 256, 256>>>(inputs);
    conv_b<<<D_, 384>>>(ik, bias);

    dim3 gg(G_ / 128, M_ / 128);   // (3, 2048)
    xproj_mma<<<gg, 256, 98304>>>();

    efm_scan<<<B_ / 2, 384, 98304>>>(sigs, rk, fk, bias, out);
}

// round 13
// speedup vs baseline: 1.2559x; 1.2559x over previous
#include <cuda_runtime.h>
#include <cuda_bf16.h>
#include <cstdint>

// ---------------------------------------------------------------------------
// EfmLSTM round 13: GEMM/conv = round 11. Scan = round-11 staggered body with
// lane-paired K-SPLIT GEMV: thread j holds khalf=j&1 of W for columns j and
// j^1 (128 regs, unchanged); h stored split+padded so each warp LDS touches 2
// disjoint-bank lines -> crossbar wavefronts halved; shfl_xor(1) recombines.
// ---------------------------------------------------------------------------

#define B_   256
#define T_   1024
#define D_   256
#define U_   128
#define G_   384
#define SIG_ 20
#define M_   (B_ * T_)

typedef unsigned long long ull;

__device__ float g_xproj[(size_t)M_ * G_];
__device__ __nv_bfloat16 g_acat[(size_t)M_ * 512];
__device__ __nv_bfloat16 g_btcat[(size_t)G_ * 768];
__device__ float g_gbias[G_];

__device__ __forceinline__ ull pack2f(float lo, float hi) {
    ull r; asm("mov.b64 %0, {%1,%2};" : "=l"(r) : "f"(lo), "f"(hi)); return r;
}
__device__ __forceinline__ void unpack2f(ull v, float& lo, float& hi) {
    asm("mov.b64 {%0,%1}, %2;" : "=f"(lo), "=f"(hi) : "l"(v));
}
__device__ __forceinline__ ull ffma2(ull a, ull b, ull c) {
    ull d; asm("fma.rn.f32x2 %0, %1, %2, %3;" : "=l"(d) : "l"(a), "l"(b), "l"(c)); return d;
}
__device__ __forceinline__ float fsig(float x) {
    return __fdividef(1.0f, 1.0f + __expf(-x));
}
__device__ __forceinline__ float ftanh(float x) {
    return 1.0f - 2.0f * __fdividef(1.0f, __expf(2.0f * x) + 1.0f);
}
__device__ __forceinline__ uint32_t smem_u32(const void* p) {
    uint32_t a;
    asm("{ .reg .u64 t; cvta.to.shared.u64 t, %1; cvt.u32.u64 %0, t; }" : "=r"(a) : "l"(p));
    return a;
}
__device__ __forceinline__ void ldsm4(uint32_t* r, uint32_t addr) {
    asm volatile("ldmatrix.sync.aligned.m8n8.x4.shared.b16 {%0,%1,%2,%3}, [%4];"
        : "=r"(r[0]), "=r"(r[1]), "=r"(r[2]), "=r"(r[3]) : "r"(addr));
}
__device__ __forceinline__ void mma16816(float* d, const uint32_t* a, const uint32_t* b) {
    asm volatile(
        "mma.sync.aligned.m16n8k16.row.col.f32.bf16.bf16.f32 "
        "{%0,%1,%2,%3}, {%4,%5,%6,%7}, {%8,%9}, {%0,%1,%2,%3};"
        : "+f"(d[0]), "+f"(d[1]), "+f"(d[2]), "+f"(d[3])
        : "r"(a[0]), "r"(a[1]), "r"(a[2]), "r"(a[3]), "r"(b[0]), "r"(b[1]));
}
__device__ __forceinline__ void cpasync16(uint32_t dst, const void* src) {
    asm volatile("cp.async.cg.shared.global [%0], [%1], 16;" :: "r"(dst), "l"(src) : "memory");
}
#define CP_COMMIT() asm volatile("cp.async.commit_group;" ::: "memory")
#define CP_WAITG(n) asm volatile("cp.async.wait_group %0;" :: "n"(n) : "memory")

// ===========================================================================
__global__ __launch_bounds__(256)
void conv_a(const float* __restrict__ in) {
    size_t v = (size_t)blockIdx.x * 256 + threadIdx.x;
    size_t m = v >> 6;
    int c4 = (int)(v & 63);
    float4 a = ((const float4*)in)[v];
    __nv_bfloat16 h0 = __float2bfloat16(a.x), h1 = __float2bfloat16(a.y);
    __nv_bfloat16 h2 = __float2bfloat16(a.z), h3 = __float2bfloat16(a.w);
    __nv_bfloat16 l0 = __float2bfloat16(a.x - __bfloat162float(h0));
    __nv_bfloat16 l1 = __float2bfloat16(a.y - __bfloat162float(h1));
    __nv_bfloat16 l2 = __float2bfloat16(a.z - __bfloat162float(h2));
    __nv_bfloat16 l3 = __float2bfloat16(a.w - __bfloat162float(h3));
    __nv_bfloat162* dst = (__nv_bfloat162*)(g_acat + m * 512 + c4 * 4);
    dst[0] = __nv_bfloat162(h0, h1);
    dst[1] = __nv_bfloat162(h2, h3);
    __nv_bfloat162* dstl = (__nv_bfloat162*)(g_acat + m * 512 + 256 + c4 * 4);
    dstl[0] = __nv_bfloat162(l0, l1);
    dstl[1] = __nv_bfloat162(l2, l3);
}

// ===========================================================================
__global__ __launch_bounds__(384)
void conv_b(const float* __restrict__ ik, const float* __restrict__ bias) {
    int k = blockIdx.x;
    int n = threadIdx.x;
    float b = ik[(size_t)k * G_ + n];
    __nv_bfloat16 bh = __float2bfloat16(b);
    __nv_bfloat16 bl = __float2bfloat16(b - __bfloat162float(bh));
    __nv_bfloat16* row = g_btcat + (size_t)n * 768;
    row[k] = bh;
    row[256 + k] = bh;
    row[512 + k] = bl;
    if (k == 0) {
        float gb;
        if (n < U_)          gb = bias[n];
        else if (n < 2 * U_) gb = bias[2 * U_ + (n - U_)];
        else                 gb = bias[3 * U_ + (n - 2 * U_)];
        g_gbias[n] = gb;
    }
}

// ===========================================================================
// K1: x_proj GEMM (round-7 pipeline) + gate bias in epilogue.
// ===========================================================================
#define ABUF(s) ((s) * 16384)
#define BBUF(s) (49152 + (s) * 16384)

__global__ __launch_bounds__(256, 2)
void xproj_mma(void) {
    extern __shared__ __align__(1024) char dsm[];
    const uint32_t sb = smem_u32(dsm);

    const int tid = threadIdx.x;
    const int wid = tid >> 5;
    const int lane = tid & 31;
    const int wm = wid & 3;
    const int wn = wid >> 2;
    const int n0 = blockIdx.x * 128;
    const size_t m0 = (size_t)blockIdx.y * 128;

    const int lrow = tid >> 3;
    const int c16  = tid & 7;
    uint32_t cpOff[4];
#pragma unroll
    for (int i = 0; i < 4; i++) {
        int row = lrow + 32 * i;
        cpOff[i] = (uint32_t)(row * 128 + ((c16 * 16) ^ ((row & 7) << 4)));
    }
    const __nv_bfloat16* aSrc[4];
    const __nv_bfloat16* bSrc[4];
#pragma unroll
    for (int i = 0; i < 4; i++) {
        int row = lrow + 32 * i;
        aSrc[i] = g_acat + (m0 + row) * 512 + c16 * 8;
        bSrc[i] = g_btcat + (size_t)(n0 + row) * 768 + c16 * 8;
    }

    const int a_row0 = wm * 32 + (lane & 15);
    const int a_hi   = lane >> 4;
    const uint32_t a_xor = (uint32_t)((a_row0 & 7) << 4);
    const uint32_t aOff0 = (uint32_t)(a_row0 * 128);
    const uint32_t aOff1 = (uint32_t)((a_row0 + 16) * 128);

    const int b_row_l = wn * 64 + (lane & 7) + ((lane >> 4) << 3);
    const int b_hi    = (lane >> 3) & 1;
    const uint32_t b_xor = (uint32_t)((b_row_l & 7) << 4);
    uint32_t bOff[4];
#pragma unroll
    for (int p = 0; p < 4; p++)
        bOff[p] = (uint32_t)((b_row_l + p * 16) * 128);

    float d[2][8][4];
#pragma unroll
    for (int af = 0; af < 2; af++)
#pragma unroll
        for (int p = 0; p < 8; p++)
#pragma unroll
            for (int q = 0; q < 4; q++) d[af][p][q] = 0.0f;

#pragma unroll
    for (int pc = 0; pc < 2; pc++) {
#pragma unroll
        for (int i = 0; i < 4; i++) cpasync16(sb + ABUF(pc) + cpOff[i], aSrc[i] + pc * 64);
#pragma unroll
        for (int i = 0; i < 4; i++) cpasync16(sb + BBUF(pc) + cpOff[i], bSrc[i] + pc * 64);
        CP_COMMIT();
    }

#pragma unroll
    for (int c = 0; c < 12; c++) {
        const int buf = c % 3;

        if (c < 11) { CP_WAITG(1); } else { CP_WAITG(0); }
        __syncthreads();

        if (c + 2 < 12) {
            const int cn = c + 2;
            const int nbuf = cn % 3;
            const int akc = (cn < 8) ? cn * 64 : (cn - 8) * 64;
            const int bkc = cn * 64;
#pragma unroll
            for (int i = 0; i < 4; i++) cpasync16(sb + ABUF(nbuf) + cpOff[i], aSrc[i] + akc);
#pragma unroll
            for (int i = 0; i < 4; i++) cpasync16(sb + BBUF(nbuf) + cpOff[i], bSrc[i] + bkc);
            CP_COMMIT();
        }

        const uint32_t aB0 = sb + ABUF(buf) + aOff0;
        const uint32_t aB1 = sb + ABUF(buf) + aOff1;
        const uint32_t bBs = sb + BBUF(buf);
#pragma unroll
        for (int ks = 0; ks < 4; ks++) {
            uint32_t af0[4], af1[4];
            uint32_t koffA = (uint32_t)(((ks * 2 + a_hi) * 16) ^ a_xor);
            ldsm4(af0, aB0 + koffA);
            ldsm4(af1, aB1 + koffA);
            uint32_t koffB = (uint32_t)(((ks * 2 + b_hi) * 16) ^ b_xor);
#pragma unroll
            for (int p = 0; p < 4; p++) {
                uint32_t bf[4];
                ldsm4(bf, bBs + bOff[p] + koffB);
                mma16816(d[0][p * 2],     af0, &bf[0]);
                mma16816(d[0][p * 2 + 1], af0, &bf[2]);
                mma16816(d[1][p * 2],     af1, &bf[0]);
                mma16816(d[1][p * 2 + 1], af1, &bf[2]);
            }
        }
    }

    const int colb = n0 + wn * 64 + 2 * (lane & 3);
#pragma unroll
    for (int af = 0; af < 2; af++) {
        const int mrow = (int)m0 + wm * 32 + af * 16 + (lane >> 2);
#pragma unroll
        for (int p = 0; p < 8; p++) {
            int col = colb + p * 8;
            float2 gb = *(const float2*)(g_gbias + col);
            *(float2*)(g_xproj + (size_t)mrow * G_ + col) =
                make_float2(d[af][p][0] + gb.x, d[af][p][1] + gb.y);
            *(float2*)(g_xproj + (size_t)(mrow + 8) * G_ + col) =
                make_float2(d[af][p][2] + gb.x, d[af][p][3] + gb.y);
        }
    }
}

// ===========================================================================
// K2: row-staggered scan with lane-paired k-split GEMV.
// h layout: sh[row][k + 8*(k>=64)] (32B pad between halves -> disjoint banks).
// Thread j: khalf=j&1, holds W[khalf-ks] for columns j (own) and j^1 (other).
// Per phase: 16 LDS.128 (2 lines/warp-instr, 1 wavefront) + 64 FFMA2 + 1 shfl.
// ===========================================================================
#define HIDX(k) ((k) + 8 * ((k) >= 64 ? 1 : 0))

__global__ __launch_bounds__(384, 1)
void efm_scan(const float* __restrict__ sigs,
              const float* __restrict__ rk,
              const float* __restrict__ fk,
              const float* __restrict__ bias,
              float* __restrict__ out)
{
    const int j = threadIdx.x;
    const int r0 = blockIdx.x * 2;

    __shared__ __align__(16) float sh[2][136];       // split+padded h
    __shared__ __align__(16) float sg[2][G_];
    __shared__ __align__(16) float sF[SIG_][U_];
    __shared__ float ssig[2][2][SIG_];
    __shared__ float sfv[2][2][U_];

    // --- W: khalf ks for own column j and partner column j^1 ---
    const int kh = j & 1;
    const int k0 = kh * 64;
    const int jo = j ^ 1;
    ull Wown[32], Woth[32];
#pragma unroll
    for (int q = 0; q < 32; q++) {
        int k = k0 + 2 * q;
        Wown[q] = pack2f(rk[(size_t)k * G_ + j],  rk[(size_t)(k + 1) * G_ + j]);
        Woth[q] = pack2f(rk[(size_t)k * G_ + jo], rk[(size_t)(k + 1) * G_ + jo]);
    }

    for (int idx = j; idx < SIG_ * U_; idx += 384)
        (&sF[0][0])[idx] = fk[idx];

    if (j < U_) {
        sh[0][HIDX(j)] = 0.0f;
        sh[1][HIDX(j)] = 0.0f;
    }

    const bool actSig = (j < U_) || (j >= 2 * U_);
    const bool isU0 = (j < U_);
    const bool isU1 = (j >= U_) && (j < 2 * U_);
    const int u = j & (U_ - 1);
    float creg = 0.0f;
    float* op = out + ((size_t)(r0 + (isU1 ? 1 : 0)) * T_) * U_ + u;

    const bool isF = (j >= 2 * U_);
    const int fu = isF ? (j - 2 * U_) : 0;
    const float fbias = bias[U_ + fu];

    const bool isL = (j >= 296) && (j < 296 + 2 * SIG_);
    const int lrw = isL ? (j - 296) / SIG_ : 0;
    const int ls  = isL ? (j - 296) % SIG_ : 0;
    const float* sigp = sigs + ((size_t)(r0 + lrw) * T_) * SIG_ + ls;

    const float* xp0 = g_xproj + ((size_t)r0 * T_) * G_ + j;
    const float* xp1 = g_xproj + ((size_t)(r0 + 1) * T_) * G_ + j;

    // GEMV h base for this thread's k-half (float offset 0 or 72)
    const float* hb0 = &sh[0][kh * 72];
    const float* hb1 = &sh[1][kh * 72];

    // ---- prologue ----
    if (isL) ssig[0][lrw][ls] = sigp[0];
    float sreg = isL ? sigp[SIG_] : 0.0f;
    float xr00 = xp0[0];
    float x1 = xp1[0];
    float x0 = xp0[G_];
    __syncthreads();

    sg[0][j] = actSig ? fsig(xr00) : ftanh(xr00);
    if (isF) {
        float a0 = fbias, a1 = fbias;
#pragma unroll
        for (int s = 0; s < SIG_; s++) {
            float cf = sF[s][fu];
            a0 += ssig[0][0][s] * cf;
            a1 += ssig[0][1][s] * cf;
        }
        sfv[0][0][fu] = fsig(a0);
        sfv[0][1][fu] = fsig(a1);
    }
    __syncthreads();

    for (int t = 0; t < T_; t++) {
        const int pb = (t + 1) & 1;

        // ================= Phase A(t) =================
        if (isL) {
            ssig[pb][lrw][ls] = sreg;
            int t2 = (t + 2 < T_) ? t + 2 : T_ - 1;
            sreg = sigp[(size_t)t2 * SIG_];
        }
        int tn1 = (t + 1 < T_) ? t + 1 : T_ - 1;
        float nx1 = xp1[(size_t)tn1 * G_];

        {   // GEMV r1(t), k-split
            ull ao = 0ULL, bo = 0ULL, ax = 0ULL, bx = 0ULL;
#pragma unroll
            for (int q = 0; q < 16; q++) {
                ulonglong2 h2 = *(const ulonglong2*)(hb1 + 4 * q);
                ao = ffma2(h2.x, Wown[2 * q],     ao);
                bo = ffma2(h2.y, Wown[2 * q + 1], bo);
                ax = ffma2(h2.x, Woth[2 * q],     ax);
                bx = ffma2(h2.y, Woth[2 * q + 1], bx);
            }
            float lo, hi;
            unpack2f(ao, lo, hi); float pown = lo + hi;
            unpack2f(bo, lo, hi); pown += lo + hi;
            unpack2f(ax, lo, hi); float poth = lo + hi;
            unpack2f(bx, lo, hi); poth += lo + hi;
            float recv = __shfl_xor_sync(0xFFFFFFFFu, poth, 1);
            float g = pown + recv + x1;
            sg[1][j] = actSig ? fsig(g) : ftanh(g);
        }
        if (isU0) {   // update r0(t)
            float fcur = sfv[t & 1][0][u];
            float ig = sg[0][u];
            float ch = sg[0][U_ + u];
            float og = sg[0][2 * U_ + u];
            creg = fcur * creg + ig * ch;
            float hn = og * ftanh(creg);
            sh[0][HIDX(u)] = hn;
            op[(size_t)t * U_] = hn;
        }
        __syncthreads();

        // ================= Phase B(t) =================
        int tn2 = (t + 2 < T_) ? t + 2 : T_ - 1;
        float nx0 = xp0[(size_t)tn2 * G_];

        if (t + 1 < T_) {   // GEMV r0(t+1), k-split
            ull ao = 0ULL, bo = 0ULL, ax = 0ULL, bx = 0ULL;
#pragma unroll
            for (int q = 0; q < 16; q++) {
                ulonglong2 h2 = *(const ulonglong2*)(hb0 + 4 * q);
                ao = ffma2(h2.x, Wown[2 * q],     ao);
                bo = ffma2(h2.y, Wown[2 * q + 1], bo);
                ax = ffma2(h2.x, Woth[2 * q],     ax);
                bx = ffma2(h2.y, Woth[2 * q + 1], bx);
            }
            float lo, hi;
            unpack2f(ao, lo, hi); float pown = lo + hi;
            unpack2f(bo, lo, hi); pown += lo + hi;
            unpack2f(ax, lo, hi); float poth = lo + hi;
            unpack2f(bx, lo, hi); poth += lo + hi;
            float recv = __shfl_xor_sync(0xFFFFFFFFu, poth, 1);
            float g = pown + recv + x0;
            sg[0][j] = actSig ? fsig(g) : ftanh(g);
        }
        if (isU1) {   // update r1(t)
            float fcur = sfv[t & 1][1][u];
            float ig = sg[1][u];
            float ch = sg[1][U_ + u];
            float og = sg[1][2 * U_ + u];
            creg = fcur * creg + ig * ch;
            float hn = og * ftanh(creg);
            sh[1][HIDX(u)] = hn;
            op[(size_t)t * U_] = hn;
        }
        if (isF) {   // f(t+1) both rows
            float a0 = fbias, a1 = fbias;
#pragma unroll
            for (int s = 0; s < SIG_; s++) {
                float cf = sF[s][fu];
                a0 += ssig[pb][0][s] * cf;
                a1 += ssig[pb][1][s] * cf;
            }
            sfv[pb][0][fu] = fsig(a0);
            sfv[pb][1][fu] = fsig(a1);
        }
        __syncthreads();

        x1 = nx1;
        x0 = nx0;
    }
}

// ===========================================================================
extern "C" void kernel_launch(void* const* d_in, const int* in_sizes, int n_in,
                              void* d_out, int out_size) {
    const float* inputs = (const float*)d_in[0];
    const float* sigs   = (const float*)d_in[1];
    const float* ik     = (const float*)d_in[2];
    const float* rk     = (const float*)d_in[3];
    const float* fk     = (const float*)d_in[4];
    const float* bias   = (const float*)d_in[5];
    float* out = (float*)d_out;

    cudaFuncSetAttribute(xproj_mma, cudaFuncAttributeMaxDynamicSharedMemorySize, 98304);

    conv_a<<<(M_ * 64) / 256, 256>>>(inputs);
    conv_b<<<D_, 384>>>(ik, bias);

    dim3 gg(G_ / 128, M_ / 128);   // (3, 2048)
    xproj_mma<<<gg, 256, 98304>>>();

    efm_scan<<<B_ / 2, 384>>>(sigs, rk, fk, bias, out);
}

// round 14
// speedup vs baseline: 1.3110x; 1.0438x over previous
#include <cuda_runtime.h>
#include <cuda_bf16.h>
#include <cstdint>

// ---------------------------------------------------------------------------
// EfmLSTM round 14: GEMM/conv = round 13. Scan: lane-QUAD k-split GEMV —
// thread j holds quarter kq=j&3 of W for columns j^0..j^3 (128 regs, same),
// h stored in 4 padded quarters (bank-disjoint), 8 LDS.128/phase (was 16),
// 2-stage shfl butterfly recombines.
// ---------------------------------------------------------------------------

#define B_   256
#define T_   1024
#define D_   256
#define U_   128
#define G_   384
#define SIG_ 20
#define M_   (B_ * T_)

typedef unsigned long long ull;

__device__ float g_xproj[(size_t)M_ * G_];
__device__ __nv_bfloat16 g_acat[(size_t)M_ * 512];
__device__ __nv_bfloat16 g_btcat[(size_t)G_ * 768];
__device__ float g_gbias[G_];

__device__ __forceinline__ ull pack2f(float lo, float hi) {
    ull r; asm("mov.b64 %0, {%1,%2};" : "=l"(r) : "f"(lo), "f"(hi)); return r;
}
__device__ __forceinline__ void unpack2f(ull v, float& lo, float& hi) {
    asm("mov.b64 {%0,%1}, %2;" : "=f"(lo), "=f"(hi) : "l"(v));
}
__device__ __forceinline__ ull ffma2(ull a, ull b, ull c) {
    ull d; asm("fma.rn.f32x2 %0, %1, %2, %3;" : "=l"(d) : "l"(a), "l"(b), "l"(c)); return d;
}
__device__ __forceinline__ float fsig(float x) {
    return __fdividef(1.0f, 1.0f + __expf(-x));
}
__device__ __forceinline__ float ftanh(float x) {
    return 1.0f - 2.0f * __fdividef(1.0f, __expf(2.0f * x) + 1.0f);
}
__device__ __forceinline__ uint32_t smem_u32(const void* p) {
    uint32_t a;
    asm("{ .reg .u64 t; cvta.to.shared.u64 t, %1; cvt.u32.u64 %0, t; }" : "=r"(a) : "l"(p));
    return a;
}
__device__ __forceinline__ void ldsm4(uint32_t* r, uint32_t addr) {
    asm volatile("ldmatrix.sync.aligned.m8n8.x4.shared.b16 {%0,%1,%2,%3}, [%4];"
        : "=r"(r[0]), "=r"(r[1]), "=r"(r[2]), "=r"(r[3]) : "r"(addr));
}
__device__ __forceinline__ void mma16816(float* d, const uint32_t* a, const uint32_t* b) {
    asm volatile(
        "mma.sync.aligned.m16n8k16.row.col.f32.bf16.bf16.f32 "
        "{%0,%1,%2,%3}, {%4,%5,%6,%7}, {%8,%9}, {%0,%1,%2,%3};"
        : "+f"(d[0]), "+f"(d[1]), "+f"(d[2]), "+f"(d[3])
        : "r"(a[0]), "r"(a[1]), "r"(a[2]), "r"(a[3]), "r"(b[0]), "r"(b[1]));
}
__device__ __forceinline__ void cpasync16(uint32_t dst, const void* src) {
    asm volatile("cp.async.cg.shared.global [%0], [%1], 16;" :: "r"(dst), "l"(src) : "memory");
}
#define CP_COMMIT() asm volatile("cp.async.commit_group;" ::: "memory")
#define CP_WAITG(n) asm volatile("cp.async.wait_group %0;" :: "n"(n) : "memory")

// ===========================================================================
__global__ __launch_bounds__(256)
void conv_a(const float* __restrict__ in) {
    size_t v = (size_t)blockIdx.x * 256 + threadIdx.x;
    size_t m = v >> 6;
    int c4 = (int)(v & 63);
    float4 a = ((const float4*)in)[v];
    __nv_bfloat16 h0 = __float2bfloat16(a.x), h1 = __float2bfloat16(a.y);
    __nv_bfloat16 h2 = __float2bfloat16(a.z), h3 = __float2bfloat16(a.w);
    __nv_bfloat16 l0 = __float2bfloat16(a.x - __bfloat162float(h0));
    __nv_bfloat16 l1 = __float2bfloat16(a.y - __bfloat162float(h1));
    __nv_bfloat16 l2 = __float2bfloat16(a.z - __bfloat162float(h2));
    __nv_bfloat16 l3 = __float2bfloat16(a.w - __bfloat162float(h3));
    __nv_bfloat162* dst = (__nv_bfloat162*)(g_acat + m * 512 + c4 * 4);
    dst[0] = __nv_bfloat162(h0, h1);
    dst[1] = __nv_bfloat162(h2, h3);
    __nv_bfloat162* dstl = (__nv_bfloat162*)(g_acat + m * 512 + 256 + c4 * 4);
    dstl[0] = __nv_bfloat162(l0, l1);
    dstl[1] = __nv_bfloat162(l2, l3);
}

// ===========================================================================
__global__ __launch_bounds__(384)
void conv_b(const float* __restrict__ ik, const float* __restrict__ bias) {
    int k = blockIdx.x;
    int n = threadIdx.x;
    float b = ik[(size_t)k * G_ + n];
    __nv_bfloat16 bh = __float2bfloat16(b);
    __nv_bfloat16 bl = __float2bfloat16(b - __bfloat162float(bh));
    __nv_bfloat16* row = g_btcat + (size_t)n * 768;
    row[k] = bh;
    row[256 + k] = bh;
    row[512 + k] = bl;
    if (k == 0) {
        float gb;
        if (n < U_)          gb = bias[n];
        else if (n < 2 * U_) gb = bias[2 * U_ + (n - U_)];
        else                 gb = bias[3 * U_ + (n - 2 * U_)];
        g_gbias[n] = gb;
    }
}

// ===========================================================================
// K1: x_proj GEMM (round-7 pipeline) + gate bias in epilogue.
// ===========================================================================
#define ABUF(s) ((s) * 16384)
#define BBUF(s) (49152 + (s) * 16384)

__global__ __launch_bounds__(256, 2)
void xproj_mma(void) {
    extern __shared__ __align__(1024) char dsm[];
    const uint32_t sb = smem_u32(dsm);

    const int tid = threadIdx.x;
    const int wid = tid >> 5;
    const int lane = tid & 31;
    const int wm = wid & 3;
    const int wn = wid >> 2;
    const int n0 = blockIdx.x * 128;
    const size_t m0 = (size_t)blockIdx.y * 128;

    const int lrow = tid >> 3;
    const int c16  = tid & 7;
    uint32_t cpOff[4];
#pragma unroll
    for (int i = 0; i < 4; i++) {
        int row = lrow + 32 * i;
        cpOff[i] = (uint32_t)(row * 128 + ((c16 * 16) ^ ((row & 7) << 4)));
    }
    const __nv_bfloat16* aSrc[4];
    const __nv_bfloat16* bSrc[4];
#pragma unroll
    for (int i = 0; i < 4; i++) {
        int row = lrow + 32 * i;
        aSrc[i] = g_acat + (m0 + row) * 512 + c16 * 8;
        bSrc[i] = g_btcat + (size_t)(n0 + row) * 768 + c16 * 8;
    }

    const int a_row0 = wm * 32 + (lane & 15);
    const int a_hi   = lane >> 4;
    const uint32_t a_xor = (uint32_t)((a_row0 & 7) << 4);
    const uint32_t aOff0 = (uint32_t)(a_row0 * 128);
    const uint32_t aOff1 = (uint32_t)((a_row0 + 16) * 128);

    const int b_row_l = wn * 64 + (lane & 7) + ((lane >> 4) << 3);
    const int b_hi    = (lane >> 3) & 1;
    const uint32_t b_xor = (uint32_t)((b_row_l & 7) << 4);
    uint32_t bOff[4];
#pragma unroll
    for (int p = 0; p < 4; p++)
        bOff[p] = (uint32_t)((b_row_l + p * 16) * 128);

    float d[2][8][4];
#pragma unroll
    for (int af = 0; af < 2; af++)
#pragma unroll
        for (int p = 0; p < 8; p++)
#pragma unroll
            for (int q = 0; q < 4; q++) d[af][p][q] = 0.0f;

#pragma unroll
    for (int pc = 0; pc < 2; pc++) {
#pragma unroll
        for (int i = 0; i < 4; i++) cpasync16(sb + ABUF(pc) + cpOff[i], aSrc[i] + pc * 64);
#pragma unroll
        for (int i = 0; i < 4; i++) cpasync16(sb + BBUF(pc) + cpOff[i], bSrc[i] + pc * 64);
        CP_COMMIT();
    }

#pragma unroll
    for (int c = 0; c < 12; c++) {
        const int buf = c % 3;

        if (c < 11) { CP_WAITG(1); } else { CP_WAITG(0); }
        __syncthreads();

        if (c + 2 < 12) {
            const int cn = c + 2;
            const int nbuf = cn % 3;
            const int akc = (cn < 8) ? cn * 64 : (cn - 8) * 64;
            const int bkc = cn * 64;
#pragma unroll
            for (int i = 0; i < 4; i++) cpasync16(sb + ABUF(nbuf) + cpOff[i], aSrc[i] + akc);
#pragma unroll
            for (int i = 0; i < 4; i++) cpasync16(sb + BBUF(nbuf) + cpOff[i], bSrc[i] + bkc);
            CP_COMMIT();
        }

        const uint32_t aB0 = sb + ABUF(buf) + aOff0;
        const uint32_t aB1 = sb + ABUF(buf) + aOff1;
        const uint32_t bBs = sb + BBUF(buf);
#pragma unroll
        for (int ks = 0; ks < 4; ks++) {
            uint32_t af0[4], af1[4];
            uint32_t koffA = (uint32_t)(((ks * 2 + a_hi) * 16) ^ a_xor);
            ldsm4(af0, aB0 + koffA);
            ldsm4(af1, aB1 + koffA);
            uint32_t koffB = (uint32_t)(((ks * 2 + b_hi) * 16) ^ b_xor);
#pragma unroll
            for (int p = 0; p < 4; p++) {
                uint32_t bf[4];
                ldsm4(bf, bBs + bOff[p] + koffB);
                mma16816(d[0][p * 2],     af0, &bf[0]);
                mma16816(d[0][p * 2 + 1], af0, &bf[2]);
                mma16816(d[1][p * 2],     af1, &bf[0]);
                mma16816(d[1][p * 2 + 1], af1, &bf[2]);
            }
        }
    }

    const int colb = n0 + wn * 64 + 2 * (lane & 3);
#pragma unroll
    for (int af = 0; af < 2; af++) {
        const int mrow = (int)m0 + wm * 32 + af * 16 + (lane >> 2);
#pragma unroll
        for (int p = 0; p < 8; p++) {
            int col = colb + p * 8;
            float2 gb = *(const float2*)(g_gbias + col);
            *(float2*)(g_xproj + (size_t)mrow * G_ + col) =
                make_float2(d[af][p][0] + gb.x, d[af][p][1] + gb.y);
            *(float2*)(g_xproj + (size_t)(mrow + 8) * G_ + col) =
                make_float2(d[af][p][2] + gb.x, d[af][p][3] + gb.y);
        }
    }
}

// ===========================================================================
// K2: row-staggered scan with lane-quad k-split GEMV.
// h layout: 4 quarters of 32 floats, each padded +4 -> quarter q at q*36.
// Thread j: kq=j&3, holds W[kq-quarter] for columns j^0..j^3.
// Per phase: 8 LDS.128 (4 disjoint-bank lines/instr) + 64 FFMA2 + 2 shfl.
// ===========================================================================
#define HIDX(k) ((k) + 4 * ((k) >> 5))

__global__ __launch_bounds__(384, 1)
void efm_scan(const float* __restrict__ sigs,
              const float* __restrict__ rk,
              const float* __restrict__ fk,
              const float* __restrict__ bias,
              float* __restrict__ out)
{
    const int j = threadIdx.x;
    const int r0 = blockIdx.x * 2;

    __shared__ __align__(16) float sh[2][144];       // 4 padded quarters
    __shared__ __align__(16) float sg[2][G_];
    __shared__ __align__(16) float sF[SIG_][U_];
    __shared__ float ssig[2][2][SIG_];
    __shared__ float sfv[2][2][U_];

    // --- W quarter kq for columns j^0..j^3 (64 ull = 128 regs) ---
    const int kq = j & 3;
    const int kb = kq * 32;
    ull W[4][16];
#pragma unroll
    for (int c = 0; c < 4; c++) {
        int col = j ^ c;
#pragma unroll
        for (int q = 0; q < 16; q++) {
            int k = kb + 2 * q;
            W[c][q] = pack2f(rk[(size_t)k * G_ + col], rk[(size_t)(k + 1) * G_ + col]);
        }
    }

    for (int idx = j; idx < SIG_ * U_; idx += 384)
        (&sF[0][0])[idx] = fk[idx];

    if (j < U_) {
        sh[0][HIDX(j)] = 0.0f;
        sh[1][HIDX(j)] = 0.0f;
    }

    const bool actSig = (j < U_) || (j >= 2 * U_);
    const bool isU0 = (j < U_);
    const bool isU1 = (j >= U_) && (j < 2 * U_);
    const int u = j & (U_ - 1);
    float creg = 0.0f;
    float* op = out + ((size_t)(r0 + (isU1 ? 1 : 0)) * T_) * U_ + u;

    const bool isF = (j >= 2 * U_);
    const int fu = isF ? (j - 2 * U_) : 0;
    const float fbias = bias[U_ + fu];

    const bool isL = (j >= 296) && (j < 296 + 2 * SIG_);
    const int lrw = isL ? (j - 296) / SIG_ : 0;
    const int ls  = isL ? (j - 296) % SIG_ : 0;
    const float* sigp = sigs + ((size_t)(r0 + lrw) * T_) * SIG_ + ls;

    const float* xp0 = g_xproj + ((size_t)r0 * T_) * G_ + j;
    const float* xp1 = g_xproj + ((size_t)(r0 + 1) * T_) * G_ + j;

    // h base for this thread's quarter (float offset kq*36, 16B aligned)
    const float* hb0 = &sh[0][kq * 36];
    const float* hb1 = &sh[1][kq * 36];

    // ---- prologue ----
    if (isL) ssig[0][lrw][ls] = sigp[0];
    float sreg = isL ? sigp[SIG_] : 0.0f;
    float xr00 = xp0[0];
    float x1 = xp1[0];
    float x0 = xp0[G_];
    __syncthreads();

    sg[0][j] = actSig ? fsig(xr00) : ftanh(xr00);
    if (isF) {
        float a0 = fbias, a1 = fbias;
#pragma unroll
        for (int s = 0; s < SIG_; s++) {
            float cf = sF[s][fu];
            a0 += ssig[0][0][s] * cf;
            a1 += ssig[0][1][s] * cf;
        }
        sfv[0][0][fu] = fsig(a0);
        sfv[0][1][fu] = fsig(a1);
    }
    __syncthreads();

    for (int t = 0; t < T_; t++) {
        const int pb = (t + 1) & 1;

        // ================= Phase A(t) =================
        if (isL) {
            ssig[pb][lrw][ls] = sreg;
            int t2 = (t + 2 < T_) ? t + 2 : T_ - 1;
            sreg = sigp[(size_t)t2 * SIG_];
        }
        int tn1 = (t + 1 < T_) ? t + 1 : T_ - 1;
        float nx1 = xp1[(size_t)tn1 * G_];

        {   // GEMV r1(t), quad k-split
            ull ac[4] = {0ULL, 0ULL, 0ULL, 0ULL};
#pragma unroll
            for (int i = 0; i < 8; i++) {
                ulonglong2 h2 = *(const ulonglong2*)(hb1 + 4 * i);
#pragma unroll
                for (int c = 0; c < 4; c++) {
                    ac[c] = ffma2(h2.x, W[c][2 * i],     ac[c]);
                    ac[c] = ffma2(h2.y, W[c][2 * i + 1], ac[c]);
                }
            }
            float p[4], lo, hi;
#pragma unroll
            for (int c = 0; c < 4; c++) { unpack2f(ac[c], lo, hi); p[c] = lo + hi; }
            float r0s = p[0] + __shfl_xor_sync(0xFFFFFFFFu, p[1], 1);
            float r2s = p[2] + __shfl_xor_sync(0xFFFFFFFFu, p[3], 1);
            float g = r0s + __shfl_xor_sync(0xFFFFFFFFu, r2s, 2) + x1;
            sg[1][j] = actSig ? fsig(g) : ftanh(g);
        }
        if (isU0) {   // update r0(t)
            float fcur = sfv[t & 1][0][u];
            float ig = sg[0][u];
            float ch = sg[0][U_ + u];
            float og = sg[0][2 * U_ + u];
            creg = fcur * creg + ig * ch;
            float hn = og * ftanh(creg);
            sh[0][HIDX(u)] = hn;
            op[(size_t)t * U_] = hn;
        }
        __syncthreads();

        // ================= Phase B(t) =================
        int tn2 = (t + 2 < T_) ? t + 2 : T_ - 1;
        float nx0 = xp0[(size_t)tn2 * G_];

        if (t + 1 < T_) {   // GEMV r0(t+1), quad k-split
            ull ac[4] = {0ULL, 0ULL, 0ULL, 0ULL};
#pragma unroll
            for (int i = 0; i < 8; i++) {
                ulonglong2 h2 = *(const ulonglong2*)(hb0 + 4 * i);
#pragma unroll
                for (int c = 0; c < 4; c++) {
                    ac[c] = ffma2(h2.x, W[c][2 * i],     ac[c]);
                    ac[c] = ffma2(h2.y, W[c][2 * i + 1], ac[c]);
                }
            }
            float p[4], lo, hi;
#pragma unroll
            for (int c = 0; c < 4; c++) { unpack2f(ac[c], lo, hi); p[c] = lo + hi; }
            float r0s = p[0] + __shfl_xor_sync(0xFFFFFFFFu, p[1], 1);
            float r2s = p[2] + __shfl_xor_sync(0xFFFFFFFFu, p[3], 1);
            float g = r0s + __shfl_xor_sync(0xFFFFFFFFu, r2s, 2) + x0;
            sg[0][j] = actSig ? fsig(g) : ftanh(g);
        }
        if (isU1) {   // update r1(t)
            float fcur = sfv[t & 1][1][u];
            float ig = sg[1][u];
            float ch = sg[1][U_ + u];
            float og = sg[1][2 * U_ + u];
            creg = fcur * creg + ig * ch;
            float hn = og * ftanh(creg);
            sh[1][HIDX(u)] = hn;
            op[(size_t)t * U_] = hn;
        }
        if (isF) {   // f(t+1) both rows
            float a0 = fbias, a1 = fbias;
#pragma unroll
            for (int s = 0; s < SIG_; s++) {
                float cf = sF[s][fu];
                a0 += ssig[pb][0][s] * cf;
                a1 += ssig[pb][1][s] * cf;
            }
            sfv[pb][0][fu] = fsig(a0);
            sfv[pb][1][fu] = fsig(a1);
        }
        __syncthreads();

        x1 = nx1;
        x0 = nx0;
    }
}

// ===========================================================================
extern "C" void kernel_launch(void* const* d_in, const int* in_sizes, int n_in,
                              void* d_out, int out_size) {
    const float* inputs = (const float*)d_in[0];
    const float* sigs   = (const float*)d_in[1];
    const float* ik     = (const float*)d_in[2];
    const float* rk     = (const float*)d_in[3];
    const float* fk     = (const float*)d_in[4];
    const float* bias   = (const float*)d_in[5];
    float* out = (float*)d_out;

    cudaFuncSetAttribute(xproj_mma, cudaFuncAttributeMaxDynamicSharedMemorySize, 98304);

    conv_a<<<(M_ * 64) / 256, 256>>>(inputs);
    conv_b<<<D_, 384>>>(ik, bias);

    dim3 gg(G_ / 128, M_ / 128);   // (3, 2048)
    xproj_mma<<<gg, 256, 98304>>>();

    efm_scan<<<B_ / 2, 384>>>(sigs, rk, fk, bias, out);
}

// round 15
// speedup vs baseline: 1.3250x; 1.0107x over previous
#include <cuda_runtime.h>
#include <cuda_bf16.h>
#include <cstdint>

// ---------------------------------------------------------------------------
// EfmLSTM round 15: GEMM/conv = round 14. Scan: 8-way lane k-split GEMV with
// column-pair packed W (W2[c][k]=(w[col 2c],w[col 2c+1])) -> 4 packed chains,
// 4 LDS.128/phase, 3-stage shfl butterfly. Registers unchanged (~168).
// ---------------------------------------------------------------------------

#define B_   256
#define T_   1024
#define D_   256
#define U_   128
#define G_   384
#define SIG_ 20
#define M_   (B_ * T_)

typedef unsigned long long ull;

__device__ float g_xproj[(size_t)M_ * G_];
__device__ __nv_bfloat16 g_acat[(size_t)M_ * 512];
__device__ __nv_bfloat16 g_btcat[(size_t)G_ * 768];
__device__ float g_gbias[G_];

__device__ __forceinline__ ull pack2f(float lo, float hi) {
    ull r; asm("mov.b64 %0, {%1,%2};" : "=l"(r) : "f"(lo), "f"(hi)); return r;
}
__device__ __forceinline__ void unpack2f(ull v, float& lo, float& hi) {
    asm("mov.b64 {%0,%1}, %2;" : "=f"(lo), "=f"(hi) : "l"(v));
}
__device__ __forceinline__ ull ffma2(ull a, ull b, ull c) {
    ull d; asm("fma.rn.f32x2 %0, %1, %2, %3;" : "=l"(d) : "l"(a), "l"(b), "l"(c)); return d;
}
__device__ __forceinline__ float fsig(float x) {
    return __fdividef(1.0f, 1.0f + __expf(-x));
}
__device__ __forceinline__ float ftanh(float x) {
    return 1.0f - 2.0f * __fdividef(1.0f, __expf(2.0f * x) + 1.0f);
}
__device__ __forceinline__ uint32_t smem_u32(const void* p) {
    uint32_t a;
    asm("{ .reg .u64 t; cvta.to.shared.u64 t, %1; cvt.u32.u64 %0, t; }" : "=r"(a) : "l"(p));
    return a;
}
__device__ __forceinline__ void ldsm4(uint32_t* r, uint32_t addr) {
    asm volatile("ldmatrix.sync.aligned.m8n8.x4.shared.b16 {%0,%1,%2,%3}, [%4];"
        : "=r"(r[0]), "=r"(r[1]), "=r"(r[2]), "=r"(r[3]) : "r"(addr));
}
__device__ __forceinline__ void mma16816(float* d, const uint32_t* a, const uint32_t* b) {
    asm volatile(
        "mma.sync.aligned.m16n8k16.row.col.f32.bf16.bf16.f32 "
        "{%0,%1,%2,%3}, {%4,%5,%6,%7}, {%8,%9}, {%0,%1,%2,%3};"
        : "+f"(d[0]), "+f"(d[1]), "+f"(d[2]), "+f"(d[3])
        : "r"(a[0]), "r"(a[1]), "r"(a[2]), "r"(a[3]), "r"(b[0]), "r"(b[1]));
}
__device__ __forceinline__ void cpasync16(uint32_t dst, const void* src) {
    asm volatile("cp.async.cg.shared.global [%0], [%1], 16;" :: "r"(dst), "l"(src) : "memory");
}
#define CP_COMMIT() asm volatile("cp.async.commit_group;" ::: "memory")
#define CP_WAITG(n) asm volatile("cp.async.wait_group %0;" :: "n"(n) : "memory")

// ===========================================================================
__global__ __launch_bounds__(256)
void conv_a(const float* __restrict__ in) {
    size_t v = (size_t)blockIdx.x * 256 + threadIdx.x;
    size_t m = v >> 6;
    int c4 = (int)(v & 63);
    float4 a = ((const float4*)in)[v];
    __nv_bfloat16 h0 = __float2bfloat16(a.x), h1 = __float2bfloat16(a.y);
    __nv_bfloat16 h2 = __float2bfloat16(a.z), h3 = __float2bfloat16(a.w);
    __nv_bfloat16 l0 = __float2bfloat16(a.x - __bfloat162float(h0));
    __nv_bfloat16 l1 = __float2bfloat16(a.y - __bfloat162float(h1));
    __nv_bfloat16 l2 = __float2bfloat16(a.z - __bfloat162float(h2));
    __nv_bfloat16 l3 = __float2bfloat16(a.w - __bfloat162float(h3));
    __nv_bfloat162* dst = (__nv_bfloat162*)(g_acat + m * 512 + c4 * 4);
    dst[0] = __nv_bfloat162(h0, h1);
    dst[1] = __nv_bfloat162(h2, h3);
    __nv_bfloat162* dstl = (__nv_bfloat162*)(g_acat + m * 512 + 256 + c4 * 4);
    dstl[0] = __nv_bfloat162(l0, l1);
    dstl[1] = __nv_bfloat162(l2, l3);
}

// ===========================================================================
__global__ __launch_bounds__(384)
void conv_b(const float* __restrict__ ik, const float* __restrict__ bias) {
    int k = blockIdx.x;
    int n = threadIdx.x;
    float b = ik[(size_t)k * G_ + n];
    __nv_bfloat16 bh = __float2bfloat16(b);
    __nv_bfloat16 bl = __float2bfloat16(b - __bfloat162float(bh));
    __nv_bfloat16* row = g_btcat + (size_t)n * 768;
    row[k] = bh;
    row[256 + k] = bh;
    row[512 + k] = bl;
    if (k == 0) {
        float gb;
        if (n < U_)          gb = bias[n];
        else if (n < 2 * U_) gb = bias[2 * U_ + (n - U_)];
        else                 gb = bias[3 * U_ + (n - 2 * U_)];
        g_gbias[n] = gb;
    }
}

// ===========================================================================
// K1: x_proj GEMM (round-7 pipeline) + gate bias in epilogue.
// ===========================================================================
#define ABUF(s) ((s) * 16384)
#define BBUF(s) (49152 + (s) * 16384)

__global__ __launch_bounds__(256, 2)
void xproj_mma(void) {
    extern __shared__ __align__(1024) char dsm[];
    const uint32_t sb = smem_u32(dsm);

    const int tid = threadIdx.x;
    const int wid = tid >> 5;
    const int lane = tid & 31;
    const int wm = wid & 3;
    const int wn = wid >> 2;
    const int n0 = blockIdx.x * 128;
    const size_t m0 = (size_t)blockIdx.y * 128;

    const int lrow = tid >> 3;
    const int c16  = tid & 7;
    uint32_t cpOff[4];
#pragma unroll
    for (int i = 0; i < 4; i++) {
        int row = lrow + 32 * i;
        cpOff[i] = (uint32_t)(row * 128 + ((c16 * 16) ^ ((row & 7) << 4)));
    }
    const __nv_bfloat16* aSrc[4];
    const __nv_bfloat16* bSrc[4];
#pragma unroll
    for (int i = 0; i < 4; i++) {
        int row = lrow + 32 * i;
        aSrc[i] = g_acat + (m0 + row) * 512 + c16 * 8;
        bSrc[i] = g_btcat + (size_t)(n0 + row) * 768 + c16 * 8;
    }

    const int a_row0 = wm * 32 + (lane & 15);
    const int a_hi   = lane >> 4;
    const uint32_t a_xor = (uint32_t)((a_row0 & 7) << 4);
    const uint32_t aOff0 = (uint32_t)(a_row0 * 128);
    const uint32_t aOff1 = (uint32_t)((a_row0 + 16) * 128);

    const int b_row_l = wn * 64 + (lane & 7) + ((lane >> 4) << 3);
    const int b_hi    = (lane >> 3) & 1;
    const uint32_t b_xor = (uint32_t)((b_row_l & 7) << 4);
    uint32_t bOff[4];
#pragma unroll
    for (int p = 0; p < 4; p++)
        bOff[p] = (uint32_t)((b_row_l + p * 16) * 128);

    float d[2][8][4];
#pragma unroll
    for (int af = 0; af < 2; af++)
#pragma unroll
        for (int p = 0; p < 8; p++)
#pragma unroll
            for (int q = 0; q < 4; q++) d[af][p][q] = 0.0f;

#pragma unroll
    for (int pc = 0; pc < 2; pc++) {
#pragma unroll
        for (int i = 0; i < 4; i++) cpasync16(sb + ABUF(pc) + cpOff[i], aSrc[i] + pc * 64);
#pragma unroll
        for (int i = 0; i < 4; i++) cpasync16(sb + BBUF(pc) + cpOff[i], bSrc[i] + pc * 64);
        CP_COMMIT();
    }

#pragma unroll
    for (int c = 0; c < 12; c++) {
        const int buf = c % 3;

        if (c < 11) { CP_WAITG(1); } else { CP_WAITG(0); }
        __syncthreads();

        if (c + 2 < 12) {
            const int cn = c + 2;
            const int nbuf = cn % 3;
            const int akc = (cn < 8) ? cn * 64 : (cn - 8) * 64;
            const int bkc = cn * 64;
#pragma unroll
            for (int i = 0; i < 4; i++) cpasync16(sb + ABUF(nbuf) + cpOff[i], aSrc[i] + akc);
#pragma unroll
            for (int i = 0; i < 4; i++) cpasync16(sb + BBUF(nbuf) + cpOff[i], bSrc[i] + bkc);
            CP_COMMIT();
        }

        const uint32_t aB0 = sb + ABUF(buf) + aOff0;
        const uint32_t aB1 = sb + ABUF(buf) + aOff1;
        const uint32_t bBs = sb + BBUF(buf);
#pragma unroll
        for (int ks = 0; ks < 4; ks++) {
            uint32_t af0[4], af1[4];
            uint32_t koffA = (uint32_t)(((ks * 2 + a_hi) * 16) ^ a_xor);
            ldsm4(af0, aB0 + koffA);
            ldsm4(af1, aB1 + koffA);
            uint32_t koffB = (uint32_t)(((ks * 2 + b_hi) * 16) ^ b_xor);
#pragma unroll
            for (int p = 0; p < 4; p++) {
                uint32_t bf[4];
                ldsm4(bf, bBs + bOff[p] + koffB);
                mma16816(d[0][p * 2],     af0, &bf[0]);
                mma16816(d[0][p * 2 + 1], af0, &bf[2]);
                mma16816(d[1][p * 2],     af1, &bf[0]);
                mma16816(d[1][p * 2 + 1], af1, &bf[2]);
            }
        }
    }

    const int colb = n0 + wn * 64 + 2 * (lane & 3);
#pragma unroll
    for (int af = 0; af < 2; af++) {
        const int mrow = (int)m0 + wm * 32 + af * 16 + (lane >> 2);
#pragma unroll
        for (int p = 0; p < 8; p++) {
            int col = colb + p * 8;
            float2 gb = *(const float2*)(g_gbias + col);
            *(float2*)(g_xproj + (size_t)mrow * G_ + col) =
                make_float2(d[af][p][0] + gb.x, d[af][p][1] + gb.y);
            *(float2*)(g_xproj + (size_t)(mrow + 8) * G_ + col) =
                make_float2(d[af][p][2] + gb.x, d[af][p][3] + gb.y);
        }
    }
}

// ===========================================================================
// K2: row-staggered scan, 8-way k-split, column-pair packed W.
// h layout: 8 eighths of 16 floats, each padded +4 -> eighth e at e*20.
// Thread j: kq=j&7 of K for columns j^0..j^7 (4 packed col-pair chains).
// Per phase: 4 LDS.128 (8 disjoint-bank lines/instr) + 64 FFMA2 + 7 shfl.
// ===========================================================================
#define HIDX(k) ((k) + 4 * ((k) >> 4))

__global__ __launch_bounds__(384, 1)
void efm_scan(const float* __restrict__ sigs,
              const float* __restrict__ rk,
              const float* __restrict__ fk,
              const float* __restrict__ bias,
              float* __restrict__ out)
{
    const int j = threadIdx.x;
    const int r0 = blockIdx.x * 2;

    __shared__ __align__(16) float sh[2][160];       // 8 padded eighths
    __shared__ __align__(16) float sg[2][G_];
    __shared__ __align__(16) float sF[SIG_][U_];
    __shared__ float ssig[2][2][SIG_];
    __shared__ float sfv[2][2][U_];

    // --- W eighth kq for column pairs (j^2c, j^2c+1), c=0..3 ---
    const int kq = j & 7;
    const int kb = kq * 16;
    ull W2[4][16];
#pragma unroll
    for (int c = 0; c < 4; c++) {
        int cl = j ^ (2 * c);
        int ch = j ^ (2 * c + 1);
#pragma unroll
        for (int q = 0; q < 16; q++) {
            int k = kb + q;
            W2[c][q] = pack2f(rk[(size_t)k * G_ + cl], rk[(size_t)k * G_ + ch]);
        }
    }

    for (int idx = j; idx < SIG_ * U_; idx += 384)
        (&sF[0][0])[idx] = fk[idx];

    if (j < U_) {
        sh[0][HIDX(j)] = 0.0f;
        sh[1][HIDX(j)] = 0.0f;
    }

    const bool actSig = (j < U_) || (j >= 2 * U_);
    const bool isU0 = (j < U_);
    const bool isU1 = (j >= U_) && (j < 2 * U_);
    const int u = j & (U_ - 1);
    float creg = 0.0f;
    float* op = out + ((size_t)(r0 + (isU1 ? 1 : 0)) * T_) * U_ + u;

    const bool isF = (j >= 2 * U_);
    const int fu = isF ? (j - 2 * U_) : 0;
    const float fbias = bias[U_ + fu];

    const bool isL = (j >= 296) && (j < 296 + 2 * SIG_);
    const int lrw = isL ? (j - 296) / SIG_ : 0;
    const int ls  = isL ? (j - 296) % SIG_ : 0;
    const float* sigp = sigs + ((size_t)(r0 + lrw) * T_) * SIG_ + ls;

    const float* xp0 = g_xproj + ((size_t)r0 * T_) * G_ + j;
    const float* xp1 = g_xproj + ((size_t)(r0 + 1) * T_) * G_ + j;

    // h base for this thread's eighth (float offset kq*20, 16B aligned)
    const float* hb0 = &sh[0][kq * 20];
    const float* hb1 = &sh[1][kq * 20];

    // ---- prologue ----
    if (isL) ssig[0][lrw][ls] = sigp[0];
    float sreg = isL ? sigp[SIG_] : 0.0f;
    float xr00 = xp0[0];
    float x1 = xp1[0];
    float x0 = xp0[G_];
    __syncthreads();

    sg[0][j] = actSig ? fsig(xr00) : ftanh(xr00);
    if (isF) {
        float a0 = fbias, a1 = fbias;
#pragma unroll
        for (int s = 0; s < SIG_; s++) {
            float cf = sF[s][fu];
            a0 += ssig[0][0][s] * cf;
            a1 += ssig[0][1][s] * cf;
        }
        sfv[0][0][fu] = fsig(a0);
        sfv[0][1][fu] = fsig(a1);
    }
    __syncthreads();

    for (int t = 0; t < T_; t++) {
        const int pb = (t + 1) & 1;

        // ================= Phase A(t) =================
        if (isL) {
            ssig[pb][lrw][ls] = sreg;
            int t2 = (t + 2 < T_) ? t + 2 : T_ - 1;
            sreg = sigp[(size_t)t2 * SIG_];
        }
        int tn1 = (t + 1 < T_) ? t + 1 : T_ - 1;
        float nx1 = xp1[(size_t)tn1 * G_];

        {   // GEMV r1(t), 8-way k-split, col-pair chains
            ull ac[4] = {0ULL, 0ULL, 0ULL, 0ULL};
#pragma unroll
            for (int i = 0; i < 4; i++) {
                float4 hv = *(const float4*)(hb1 + 4 * i);
                ull hp0 = pack2f(hv.x, hv.x);
                ull hp1 = pack2f(hv.y, hv.y);
                ull hp2 = pack2f(hv.z, hv.z);
                ull hp3 = pack2f(hv.w, hv.w);
#pragma unroll
                for (int c = 0; c < 4; c++) {
                    ac[c] = ffma2(hp0, W2[c][4 * i + 0], ac[c]);
                    ac[c] = ffma2(hp1, W2[c][4 * i + 1], ac[c]);
                    ac[c] = ffma2(hp2, W2[c][4 * i + 2], ac[c]);
                    ac[c] = ffma2(hp3, W2[c][4 * i + 3], ac[c]);
                }
            }
            float p[8];
#pragma unroll
            for (int c = 0; c < 4; c++) unpack2f(ac[c], p[2 * c], p[2 * c + 1]);
            float q0 = p[0] + __shfl_xor_sync(0xFFFFFFFFu, p[1], 1);
            float q2 = p[2] + __shfl_xor_sync(0xFFFFFFFFu, p[3], 1);
            float q4 = p[4] + __shfl_xor_sync(0xFFFFFFFFu, p[5], 1);
            float q6 = p[6] + __shfl_xor_sync(0xFFFFFFFFu, p[7], 1);
            float r0s = q0 + __shfl_xor_sync(0xFFFFFFFFu, q2, 2);
            float r4s = q4 + __shfl_xor_sync(0xFFFFFFFFu, q6, 2);
            float g = r0s + __shfl_xor_sync(0xFFFFFFFFu, r4s, 4) + x1;
            sg[1][j] = actSig ? fsig(g) : ftanh(g);
        }
        if (isU0) {   // update r0(t)
            float fcur = sfv[t & 1][0][u];
            float ig = sg[0][u];
            float ch = sg[0][U_ + u];
            float og = sg[0][2 * U_ + u];
            creg = fcur * creg + ig * ch;
            float hn = og * ftanh(creg);
            sh[0][HIDX(u)] = hn;
            op[(size_t)t * U_] = hn;
        }
        __syncthreads();

        // ================= Phase B(t) =================
        int tn2 = (t + 2 < T_) ? t + 2 : T_ - 1;
        float nx0 = xp0[(size_t)tn2 * G_];

        if (t + 1 < T_) {   // GEMV r0(t+1)
            ull ac[4] = {0ULL, 0ULL, 0ULL, 0ULL};
#pragma unroll
            for (int i = 0; i < 4; i++) {
                float4 hv = *(const float4*)(hb0 + 4 * i);
                ull hp0 = pack2f(hv.x, hv.x);
                ull hp1 = pack2f(hv.y, hv.y);
                ull hp2 = pack2f(hv.z, hv.z);
                ull hp3 = pack2f(hv.w, hv.w);
#pragma unroll
                for (int c = 0; c < 4; c++) {
                    ac[c] = ffma2(hp0, W2[c][4 * i + 0], ac[c]);
                    ac[c] = ffma2(hp1, W2[c][4 * i + 1], ac[c]);
                    ac[c] = ffma2(hp2, W2[c][4 * i + 2], ac[c]);
                    ac[c] = ffma2(hp3, W2[c][4 * i + 3], ac[c]);
                }
            }
            float p[8];
#pragma unroll
            for (int c = 0; c < 4; c++) unpack2f(ac[c], p[2 * c], p[2 * c + 1]);
            float q0 = p[0] + __shfl_xor_sync(0xFFFFFFFFu, p[1], 1);
            float q2 = p[2] + __shfl_xor_sync(0xFFFFFFFFu, p[3], 1);
            float q4 = p[4] + __shfl_xor_sync(0xFFFFFFFFu, p[5], 1);
            float q6 = p[6] + __shfl_xor_sync(0xFFFFFFFFu, p[7], 1);
            float r0s = q0 + __shfl_xor_sync(0xFFFFFFFFu, q2, 2);
            float r4s = q4 + __shfl_xor_sync(0xFFFFFFFFu, q6, 2);
            float g = r0s + __shfl_xor_sync(0xFFFFFFFFu, r4s, 4) + x0;
            sg[0][j] = actSig ? fsig(g) : ftanh(g);
        }
        if (isU1) {   // update r1(t)
            float fcur = sfv[t & 1][1][u];
            float ig = sg[1][u];
            float ch = sg[1][U_ + u];
            float og = sg[1][2 * U_ + u];
            creg = fcur * creg + ig * ch;
            float hn = og * ftanh(creg);
            sh[1][HIDX(u)] = hn;
            op[(size_t)t * U_] = hn;
        }
        if (isF) {   // f(t+1) both rows
            float a0 = fbias, a1 = fbias;
#pragma unroll
            for (int s = 0; s < SIG_; s++) {
                float cf = sF[s][fu];
                a0 += ssig[pb][0][s] * cf;
                a1 += ssig[pb][1][s] * cf;
            }
            sfv[pb][0][fu] = fsig(a0);
            sfv[pb][1][fu] = fsig(a1);
        }
        __syncthreads();

        x1 = nx1;
        x0 = nx0;
    }
}

// ===========================================================================
extern "C" void kernel_launch(void* const* d_in, const int* in_sizes, int n_in,
                              void* d_out, int out_size) {
    const float* inputs = (const float*)d_in[0];
    const float* sigs   = (const float*)d_in[1];
    const float* ik     = (const float*)d_in[2];
    const float* rk     = (const float*)d_in[3];
    const float* fk     = (const float*)d_in[4];
    const float* bias   = (const float*)d_in[5];
    float* out = (float*)d_out;

    cudaFuncSetAttribute(xproj_mma, cudaFuncAttributeMaxDynamicSharedMemorySize, 98304);

    conv_a<<<(M_ * 64) / 256, 256>>>(inputs);
    conv_b<<<D_, 384>>>(ik, bias);

    dim3 gg(G_ / 128, M_ / 128);   // (3, 2048)
    xproj_mma<<<gg, 256, 98304>>>();

    efm_scan<<<B_ / 2, 384>>>(sigs, rk, fk, bias, out);
}